// round 14
// baseline (speedup 1.0000x reference)
#include <cuda_runtime.h>
#include <cuda_bf16.h>
#include <cuda_fp16.h>
#include <cstdint>

#define N_NODES 50000
#define N_EDGES 800000
#define NODE_IN 128
#define EDGE_IN 16
#define HIDDEN  128
#define OUT_DIM 128
#define KDIM    (NODE_IN + EDGE_IN)   // 144
#define NVEC4   (N_NODES * NODE_IN / 4)   // 1.6M float4 elements

// ---------------- scratch (device globals; no allocation allowed) ----------------
__device__ __align__(16) float g_A[(size_t)N_NODES * KDIM];     // [aggX | aggE], stride 144
__device__ __align__(16) __half g_hx[(size_t)N_NODES * NODE_IN]; // fp16 features (x, then h)
__device__ int g_count[N_NODES];
__device__ int g_rowstart[N_NODES];
__device__ int g_cursor[N_NODES];
__device__ int g_perm[N_EDGES];   // edge id, sorted by dst
__device__ int g_src[N_EDGES];    // src node id, sorted by dst
__device__ int g_blocksums[128];
__device__ int g_is64;

__device__ __forceinline__ int load_idx(const int* ei, size_t elem, int is64) {
    return is64 ? ei[2 * elem] : ei[elem];
}

// ---------------- init: zero counts + dtype detect (fused) ----------------
// int64 indices in [0,50000) => every odd 32-bit word is 0.
__global__ void k_init(const int* __restrict__ ei) {
    int i = blockIdx.x * blockDim.x + threadIdx.x;
    if (i < N_NODES) g_count[i] = 0;
    if (blockIdx.x == 0) {
        __shared__ int found;
        if (threadIdx.x == 0) found = 0;
        __syncthreads();
        for (int k = threadIdx.x; k < 4096; k += blockDim.x)
            if (ei[2 * k + 1] != 0) atomicOr(&found, 1);
        __syncthreads();
        if (threadIdx.x == 0) g_is64 = found ? 0 : 1;
    }
}

// ---------------- fused fp32->fp16 convert + dst histogram ----------------
// 1.6M threads: every thread converts one float4 of x; first 800K threads also
// histogram one edge. Independent streams -> cvt hides hist's atomic latency.
__global__ __launch_bounds__(256) void k_cvt_hist(const float* __restrict__ x,
                                                  const int* __restrict__ ei) {
    int gid = blockIdx.x * blockDim.x + threadIdx.x;

    // hist part (first: get the load in flight early)
    int d = -1;
    if (gid < N_EDGES) {
        int is64 = g_is64;
        d = load_idx(ei, (size_t)N_EDGES + gid, is64);
    }

    // cvt part
    float4 v = ((const float4*)x)[gid];
    __half2 p0 = __floats2half2_rn(v.x, v.y);
    __half2 p1 = __floats2half2_rn(v.z, v.w);
    uint2 o;
    o.x = *(uint32_t*)&p0;
    o.y = *(uint32_t*)&p1;
    ((uint2*)g_hx)[gid] = o;

    if (d >= 0) atomicAdd(&g_count[d], 1);
}

// ---------------- CSR scans ----------------
__global__ void k_scan1() {
    __shared__ int s[512];
    int t = threadIdx.x;
    int i = blockIdx.x * 512 + t;
    int v = (i < N_NODES) ? g_count[i] : 0;
    s[t] = v;
    __syncthreads();
    for (int off = 1; off < 512; off <<= 1) {
        int tmp = (t >= off) ? s[t - off] : 0;
        __syncthreads();
        s[t] += tmp;
        __syncthreads();
    }
    if (i < N_NODES) g_rowstart[i] = s[t] - v;
    if (t == 511) g_blocksums[blockIdx.x] = s[511];
}

// fused scan2+scan3: every block rebuilds the 128-wide prefix of blocksums
// in SMEM, picks its own exclusive offset, and applies it.
__global__ void k_scan23(int nblocks) {
    __shared__ int s[128];
    __shared__ int s_off;
    int t = threadIdx.x;
    if (t < 128) {
        int v = (t < nblocks) ? g_blocksums[t] : 0;
        s[t] = v;
    }
    __syncthreads();
    if (t < 128) {
        for (int off = 1; off < 128; off <<= 1) {
            int tmp = (t >= off) ? s[t - off] : 0;
            __syncthreads();
            s[t] += tmp;
            __syncthreads();
        }
    } else {
        // keep non-participating threads in step with the 14 barriers above
        for (int off = 1; off < 128; off <<= 1) { __syncthreads(); __syncthreads(); }
    }
    if (t == 0) s_off = (blockIdx.x > 0) ? s[blockIdx.x - 1] : 0;
    __syncthreads();
    int i = blockIdx.x * 512 + t;
    if (i < N_NODES) {
        int r = g_rowstart[i] + s_off;
        g_rowstart[i] = r;
        g_cursor[i] = r;
    }
}

// ---------------- scatter: 2 edges per thread (MLP 2 on the index loads) ----
__global__ void k_scatter(const int* __restrict__ ei) {
    int e0 = (blockIdx.x * blockDim.x + threadIdx.x) * 2;
    int e1 = e0 + 1;
    int is64 = g_is64;
    int d0 = 0, s0 = 0, d1 = 0, s1 = 0;
    bool v0 = e0 < N_EDGES, v1 = e1 < N_EDGES;
    if (v0) {
        d0 = load_idx(ei, (size_t)N_EDGES + e0, is64);
        s0 = load_idx(ei, (size_t)e0, is64);
    }
    if (v1) {
        d1 = load_idx(ei, (size_t)N_EDGES + e1, is64);
        s1 = load_idx(ei, (size_t)e1, is64);
    }
    if (v0) {
        int pos = atomicAdd(&g_cursor[d0], 1);
        g_perm[pos] = e0;
        g_src[pos] = s0;
    }
    if (v1) {
        int pos = atomicAdd(&g_cursor[d1], 1);
        g_perm[pos] = e1;
        g_src[pos] = s1;
    }
}

// ---------------- aggregation: warp per node, fp16 gather --------------------
// Sums src-node fp16 features (128 halfs; lane L owns uint2 index L of 32)
// into g_A[:, 0:128] with fp32 accumulation. If WITH_EA, lanes 0..15 also sum
// edge_attr (16 f32) into g_A[:, 128:144].
template <bool WITH_EA>
__global__ __launch_bounds__(256) void k_agg(const float* __restrict__ ea) {
    int warp = (blockIdx.x * blockDim.x + threadIdx.x) >> 5;
    int lane = threadIdx.x & 31;
    if (warp >= N_NODES) return;

    int start = g_rowstart[warp];
    int cnt = g_count[warp];
    const uint2* xf = (const uint2*)g_hx;   // 32 uint2 per 128-half row

    float4 acc = make_float4(0.f, 0.f, 0.f, 0.f);
    float eacc = 0.f;
    bool do_ea = WITH_EA && (lane < 16);

    // two-stage pipeline: prefetch next src/edge while consuming current
    int s = 0, e = 0;
    if (cnt > 0) {
        s = g_src[start];
        if (WITH_EA) e = g_perm[start];
    }
    for (int i = 0; i < cnt; i++) {
        int s2 = 0, e2 = 0;
        if (i + 1 < cnt) {
            s2 = g_src[start + i + 1];
            if (WITH_EA) e2 = g_perm[start + i + 1];
        }
        uint2 v = xf[(size_t)s * 32 + lane];
        __half2 p0 = *(__half2*)&v.x;
        __half2 p1 = *(__half2*)&v.y;
        float2 f0 = __half22float2(p0);
        float2 f1 = __half22float2(p1);
        acc.x += f0.x; acc.y += f0.y; acc.z += f1.x; acc.w += f1.y;
        if (do_ea) eacc += ea[(size_t)e * EDGE_IN + lane];
        s = s2; e = e2;
    }

    ((float4*)(g_A + (size_t)warp * KDIM))[lane] = acc;
    if (do_ea) g_A[(size_t)warp * KDIM + NODE_IN + lane] = eacc;
}

// ================= tensor-core GEMM via mma.sync (sm_80+ path) ================
// C[M,128] = A[M,144] @ W[144,128] + b, optional relu.
// bf16 3-pass split: A=Ah+Al, B=Bh+Bl; D = Ah*Bh + Ah*Bl + Al*Bh, fp32 accum.
// Whole K resident in SMEM. Padded stride 152 bf16 -> conflict-free frag loads.
// half_out: store relu result as fp16 into Ch (layer 1); else fp32 into Cf.

#define SM_STRIDE 152                       // bf16 elements per row (padded)
#define PLANE     (128 * SM_STRIDE)         // elements per plane
#define GEMM_DYN_SMEM (4 * PLANE * 2)       // 4 planes of bf16 = 155648 B

#define MMA16816(d, a, b)                                                     \
    asm volatile(                                                             \
        "mma.sync.aligned.m16n8k16.row.col.f32.bf16.bf16.f32 "                \
        "{%0,%1,%2,%3}, {%4,%5,%6,%7}, {%8,%9}, {%0,%1,%2,%3};"               \
        : "+f"((d)[0]), "+f"((d)[1]), "+f"((d)[2]), "+f"((d)[3])              \
        : "r"((a)[0]), "r"((a)[1]), "r"((a)[2]), "r"((a)[3]),                 \
          "r"((b)[0]), "r"((b)[1]))

__device__ __forceinline__ uint32_t pack_bf16x2(__nv_bfloat16 lo, __nv_bfloat16 hi) {
    __nv_bfloat162 p = __halves2bfloat162(lo, hi);   // .x = lo addr half
    return *(uint32_t*)&p;
}

__global__ __launch_bounds__(256, 1)
void k_gemm_mma(const float* __restrict__ A,
                const float* __restrict__ W,
                const float* __restrict__ bias,
                float* __restrict__ Cf,
                __half* __restrict__ Ch,
                int M, int relu, int half_out) {
    extern __shared__ __align__(16) char smraw[];
    __nv_bfloat16* sAh = (__nv_bfloat16*)smraw;       // [128 m][152 k]
    __nv_bfloat16* sAl = sAh + PLANE;
    __nv_bfloat16* sBh = sAl + PLANE;                 // [128 n][152 k] (= W^T)
    __nv_bfloat16* sBl = sBh + PLANE;

    const int tid = threadIdx.x;
    const int m0 = blockIdx.x * 128;

    // ---- stage A tile: rows m0..m0+127, k 0..143, hi/lo split ----
    for (int idx = tid; idx < 128 * 72; idx += 256) {     // 72 float2 per row
        int r = idx / 72;
        int kc = (idx - r * 72) * 2;
        int gr = m0 + r;
        float2 v = make_float2(0.f, 0.f);
        if (gr < M) v = *(const float2*)(A + (size_t)gr * KDIM + kc);
        __nv_bfloat16 h0 = __float2bfloat16(v.x);
        __nv_bfloat16 h1 = __float2bfloat16(v.y);
        __nv_bfloat16 l0 = __float2bfloat16(v.x - __bfloat162float(h0));
        __nv_bfloat16 l1 = __float2bfloat16(v.y - __bfloat162float(h1));
        int o = r * SM_STRIDE + kc;
        *(uint32_t*)(sAh + o) = pack_bf16x2(h0, h1);
        *(uint32_t*)(sAl + o) = pack_bf16x2(l0, l1);
    }
    // ---- stage B tile: B^T[n][k] = W[k][n], hi/lo split ----
    for (int idx = tid; idx < KDIM * 128; idx += 256) {
        int k = idx >> 7;          // W row
        int n = idx & 127;         // W col (coalesced global read)
        float v = W[idx];
        __nv_bfloat16 h = __float2bfloat16(v);
        __nv_bfloat16 l = __float2bfloat16(v - __bfloat162float(h));
        int o = n * SM_STRIDE + k;
        sBh[o] = h;
        sBl[o] = l;
    }
    __syncthreads();

    // ---- mma mainloop ----
    const int wid = tid >> 5;
    const int lane = tid & 31;
    const int g = lane >> 2;        // group id (0..7)
    const int t = lane & 3;         // thread in group
    const int wm = (wid >> 2) * 64; // warp M offset (0/64)
    const int wn = (wid & 3) * 32;  // warp N offset (0/32/64/96)

    float acc[4][4][4];
#pragma unroll
    for (int i = 0; i < 4; i++)
#pragma unroll
        for (int j = 0; j < 4; j++)
#pragma unroll
            for (int q = 0; q < 4; q++) acc[i][j][q] = 0.f;

#pragma unroll
    for (int ks = 0; ks < 9; ks++) {
        const int kb = ks * 16;     // k base (bf16 elems)
        uint32_t ah[4][4], al[4][4], bh[4][2], bl[4][2];
#pragma unroll
        for (int i = 0; i < 4; i++) {
            int r = wm + i * 16;
            int o0 = (r + g) * SM_STRIDE + kb + 2 * t;
            int o1 = (r + g + 8) * SM_STRIDE + kb + 2 * t;
            ah[i][0] = *(const uint32_t*)(sAh + o0);
            ah[i][1] = *(const uint32_t*)(sAh + o1);
            ah[i][2] = *(const uint32_t*)(sAh + o0 + 8);
            ah[i][3] = *(const uint32_t*)(sAh + o1 + 8);
            al[i][0] = *(const uint32_t*)(sAl + o0);
            al[i][1] = *(const uint32_t*)(sAl + o1);
            al[i][2] = *(const uint32_t*)(sAl + o0 + 8);
            al[i][3] = *(const uint32_t*)(sAl + o1 + 8);
        }
#pragma unroll
        for (int j = 0; j < 4; j++) {
            int n = wn + j * 8 + g;
            int o = n * SM_STRIDE + kb + 2 * t;
            bh[j][0] = *(const uint32_t*)(sBh + o);
            bh[j][1] = *(const uint32_t*)(sBh + o + 8);
            bl[j][0] = *(const uint32_t*)(sBl + o);
            bl[j][1] = *(const uint32_t*)(sBl + o + 8);
        }
#pragma unroll
        for (int i = 0; i < 4; i++)
#pragma unroll
            for (int j = 0; j < 4; j++) {
                MMA16816(acc[i][j], ah[i], bh[j]);
                MMA16816(acc[i][j], ah[i], bl[j]);
                MMA16816(acc[i][j], al[i], bh[j]);
            }
    }

    // ---- epilogue: bias + relu; fp16 (layer1) or fp32 (layer2) stores ----
#pragma unroll
    for (int j = 0; j < 4; j++) {
        int c = wn + j * 8 + 2 * t;
        float2 bb = *(const float2*)(bias + c);
#pragma unroll
        for (int i = 0; i < 4; i++) {
            int r0 = m0 + wm + i * 16 + g;
            float v0 = acc[i][j][0] + bb.x;
            float v1 = acc[i][j][1] + bb.y;
            float v2 = acc[i][j][2] + bb.x;
            float v3 = acc[i][j][3] + bb.y;
            if (relu) {
                v0 = fmaxf(v0, 0.f); v1 = fmaxf(v1, 0.f);
                v2 = fmaxf(v2, 0.f); v3 = fmaxf(v3, 0.f);
            }
            if (half_out) {
                if (r0 < M)
                    *(__half2*)(Ch + (size_t)r0 * 128 + c) = __floats2half2_rn(v0, v1);
                if (r0 + 8 < M)
                    *(__half2*)(Ch + (size_t)(r0 + 8) * 128 + c) = __floats2half2_rn(v2, v3);
            } else {
                if (r0 < M)
                    *(float2*)(Cf + (size_t)r0 * 128 + c) = make_float2(v0, v1);
                if (r0 + 8 < M)
                    *(float2*)(Cf + (size_t)(r0 + 8) * 128 + c) = make_float2(v2, v3);
            }
        }
    }
}

// ---------------- launch ----------------
extern "C" void kernel_launch(void* const* d_in, const int* in_sizes, int n_in,
                              void* d_out, int out_size) {
    const float* x  = (const float*)d_in[0];
    const int*   ei = (const int*)d_in[1];
    const float* ea = (const float*)d_in[2];
    const float* W1 = (const float*)d_in[3];
    const float* b1 = (const float*)d_in[4];
    const float* W2 = (const float*)d_in[5];
    const float* b2 = (const float*)d_in[6];
    float* out = (float*)d_out;

    const int NB_SCAN = (N_NODES + 511) / 512;      // 98
    const int CH_B = NVEC4 / 256;                   // 6250 (cvt+hist)
    const int SC_B = (N_EDGES / 2 + 255) / 256;     // 1563 (scatter, 2 edges/thr)
    const int AGG_B = (N_NODES * 32 + 255) / 256;   // 6250 (warp per node)
    const int GEMM_B = (N_NODES + 127) / 128;       // 391

    void* p;
    cudaGetSymbolAddress(&p, g_A);  float*  s_A  = (float*)p;
    cudaGetSymbolAddress(&p, g_hx); __half* s_hx = (__half*)p;

    cudaFuncSetAttribute(k_gemm_mma, cudaFuncAttributeMaxDynamicSharedMemorySize,
                         GEMM_DYN_SMEM);

    k_init<<<(N_NODES + 255) / 256, 256>>>(ei);
    k_cvt_hist<<<CH_B, 256>>>(x, ei);
    k_scan1<<<NB_SCAN, 512>>>();
    k_scan23<<<NB_SCAN, 512>>>(NB_SCAN);
    k_scatter<<<SC_B, 256>>>(ei);

    // layer 1: aggregate fp16 x + fp32 edge_attr, GEMM (relu) -> fp16 h in g_hx
    k_agg<true><<<AGG_B, 256>>>(ea);
    k_gemm_mma<<<GEMM_B, 256, GEMM_DYN_SMEM>>>(s_A, W1, b1, nullptr, s_hx,
                                               N_NODES, 1, 1);

    // layer 2: aggregate fp16 h into cols 0..127 (edge cols preserved), GEMM -> out
    k_agg<false><<<AGG_B, 256>>>(nullptr);
    k_gemm_mma<<<GEMM_B, 256, GEMM_DYN_SMEM>>>(s_A, W2, b2, out, nullptr,
                                               N_NODES, 0, 0);
}

// round 15
// speedup vs baseline: 1.3682x; 1.3682x over previous
#include <cuda_runtime.h>
#include <cuda_bf16.h>
#include <cuda_fp16.h>
#include <cstdint>

#define N_NODES 50000
#define N_EDGES 800000
#define NODE_IN 128
#define EDGE_IN 16
#define HIDDEN  128
#define OUT_DIM 128
#define KDIM    (NODE_IN + EDGE_IN)   // 144

// ---------------- scratch (device globals; no allocation allowed) ----------------
__device__ __align__(16) float g_A[(size_t)N_NODES * KDIM];     // [aggX | aggE], stride 144
__device__ __align__(16) __half g_hx[(size_t)N_NODES * NODE_IN]; // fp16 features (x, then h)
__device__ int g_count[N_NODES];
__device__ int g_rowstart[N_NODES];
__device__ int g_cursor[N_NODES];
__device__ int g_perm[N_EDGES];   // edge id, sorted by dst
__device__ int g_src[N_EDGES];    // src node id, sorted by dst
__device__ int g_blocksums[128];
__device__ int g_is64;

__device__ __forceinline__ int load_idx(const int* ei, size_t elem, int is64) {
    return is64 ? ei[2 * elem] : ei[elem];
}

// ---------------- init: zero counts + dtype detect (fused, both trivial) -----
// int64 indices in [0,50000) => every odd 32-bit word is 0.
__global__ void k_init(const int* __restrict__ ei) {
    int i = blockIdx.x * blockDim.x + threadIdx.x;
    if (i < N_NODES) g_count[i] = 0;
    if (blockIdx.x == 0) {
        __shared__ int found;
        if (threadIdx.x == 0) found = 0;
        __syncthreads();
        for (int k = threadIdx.x; k < 4096; k += blockDim.x)
            if (ei[2 * k + 1] != 0) atomicOr(&found, 1);
        __syncthreads();
        if (threadIdx.x == 0) g_is64 = found ? 0 : 1;
    }
}

// ---------------- fp32 -> fp16 feature conversion (R12 form) ----------------
__global__ __launch_bounds__(256) void k_cvt(const float* __restrict__ x) {
    size_t i = (size_t)blockIdx.x * blockDim.x + threadIdx.x;
    float4 v = ((const float4*)x)[i];
    uint2 o;
    __half2 p0 = __floats2half2_rn(v.x, v.y);
    __half2 p1 = __floats2half2_rn(v.z, v.w);
    o.x = *(uint32_t*)&p0;
    o.y = *(uint32_t*)&p1;
    ((uint2*)g_hx)[i] = o;
}

// ---------------- CSR build (R12 forms) ----------------
__global__ void k_hist(const int* __restrict__ ei) {
    int e = blockIdx.x * blockDim.x + threadIdx.x;
    if (e >= N_EDGES) return;
    int is64 = g_is64;
    int d = load_idx(ei, (size_t)N_EDGES + e, is64);
    atomicAdd(&g_count[d], 1);
}

__global__ void k_scan1() {
    __shared__ int s[512];
    int t = threadIdx.x;
    int i = blockIdx.x * 512 + t;
    int v = (i < N_NODES) ? g_count[i] : 0;
    s[t] = v;
    __syncthreads();
    for (int off = 1; off < 512; off <<= 1) {
        int tmp = (t >= off) ? s[t - off] : 0;
        __syncthreads();
        s[t] += tmp;
        __syncthreads();
    }
    if (i < N_NODES) g_rowstart[i] = s[t] - v;
    if (t == 511) g_blocksums[blockIdx.x] = s[511];
}

// fused scan2+scan3 with UNIFORM barriers: every thread executes the same
// __syncthreads() sequence; only t<128 touch the scan array.
__global__ void k_scan23(int nblocks) {
    __shared__ int s[128];
    __shared__ int s_off;
    int t = threadIdx.x;
    if (t < 128) s[t] = (t < nblocks) ? g_blocksums[t] : 0;
    __syncthreads();
    for (int off = 1; off < 128; off <<= 1) {
        int tmp = (t < 128 && t >= off) ? s[t - off] : 0;
        __syncthreads();
        if (t < 128 && t >= off) s[t] += tmp;
        __syncthreads();
    }
    if (t == 0) s_off = (blockIdx.x > 0) ? s[blockIdx.x - 1] : 0;
    __syncthreads();
    int i = blockIdx.x * 512 + t;
    if (i < N_NODES) {
        int r = g_rowstart[i] + s_off;
        g_rowstart[i] = r;
        g_cursor[i] = r;
    }
}

__global__ void k_scatter(const int* __restrict__ ei) {
    int e = blockIdx.x * blockDim.x + threadIdx.x;
    if (e >= N_EDGES) return;
    int is64 = g_is64;
    int d = load_idx(ei, (size_t)N_EDGES + e, is64);
    int s = load_idx(ei, (size_t)e, is64);
    int pos = atomicAdd(&g_cursor[d], 1);
    g_perm[pos] = e;
    g_src[pos] = s;
}

// ---------------- aggregation: warp per node, fp16 gather (R12 form) ---------
// Sums src-node fp16 features (128 halfs; lane L owns uint2 index L of 32)
// into g_A[:, 0:128] with fp32 accumulation. If WITH_EA, lanes 0..15 also sum
// edge_attr (16 f32) into g_A[:, 128:144].
template <bool WITH_EA>
__global__ __launch_bounds__(256) void k_agg(const float* __restrict__ ea) {
    int warp = (blockIdx.x * blockDim.x + threadIdx.x) >> 5;
    int lane = threadIdx.x & 31;
    if (warp >= N_NODES) return;

    int start = g_rowstart[warp];
    int cnt = g_count[warp];
    const uint2* xf = (const uint2*)g_hx;   // 32 uint2 per 128-half row

    float4 acc = make_float4(0.f, 0.f, 0.f, 0.f);
    float eacc = 0.f;
    bool do_ea = WITH_EA && (lane < 16);

    // two-stage pipeline: prefetch next src/edge while consuming current
    int s = 0, e = 0;
    if (cnt > 0) {
        s = g_src[start];
        if (WITH_EA) e = g_perm[start];
    }
    for (int i = 0; i < cnt; i++) {
        int s2 = 0, e2 = 0;
        if (i + 1 < cnt) {
            s2 = g_src[start + i + 1];
            if (WITH_EA) e2 = g_perm[start + i + 1];
        }
        uint2 v = xf[(size_t)s * 32 + lane];
        __half2 p0 = *(__half2*)&v.x;
        __half2 p1 = *(__half2*)&v.y;
        float2 f0 = __half22float2(p0);
        float2 f1 = __half22float2(p1);
        acc.x += f0.x; acc.y += f0.y; acc.z += f1.x; acc.w += f1.y;
        if (do_ea) eacc += ea[(size_t)e * EDGE_IN + lane];
        s = s2; e = e2;
    }

    ((float4*)(g_A + (size_t)warp * KDIM))[lane] = acc;
    if (do_ea) g_A[(size_t)warp * KDIM + NODE_IN + lane] = eacc;
}

// ================= tensor-core GEMM via mma.sync (sm_80+ path) ================
// C[M,128] = A[M,144] @ W[144,128] + b, optional relu.
// bf16 3-pass split: A=Ah+Al, B=Bh+Bl; D = Ah*Bh + Ah*Bl + Al*Bh, fp32 accum.
// Whole K resident in SMEM. Padded stride 152 bf16 -> conflict-free frag loads.
// half_out: store relu result as fp16 into Ch (layer 1); else fp32 into Cf.

#define SM_STRIDE 152                       // bf16 elements per row (padded)
#define PLANE     (128 * SM_STRIDE)         // elements per plane
#define GEMM_DYN_SMEM (4 * PLANE * 2)       // 4 planes of bf16 = 155648 B

#define MMA16816(d, a, b)                                                     \
    asm volatile(                                                             \
        "mma.sync.aligned.m16n8k16.row.col.f32.bf16.bf16.f32 "                \
        "{%0,%1,%2,%3}, {%4,%5,%6,%7}, {%8,%9}, {%0,%1,%2,%3};"               \
        : "+f"((d)[0]), "+f"((d)[1]), "+f"((d)[2]), "+f"((d)[3])              \
        : "r"((a)[0]), "r"((a)[1]), "r"((a)[2]), "r"((a)[3]),                 \
          "r"((b)[0]), "r"((b)[1]))

__device__ __forceinline__ uint32_t pack_bf16x2(__nv_bfloat16 lo, __nv_bfloat16 hi) {
    __nv_bfloat162 p = __halves2bfloat162(lo, hi);   // .x = lo addr half
    return *(uint32_t*)&p;
}

__global__ __launch_bounds__(256, 1)
void k_gemm_mma(const float* __restrict__ A,
                const float* __restrict__ W,
                const float* __restrict__ bias,
                float* __restrict__ Cf,
                __half* __restrict__ Ch,
                int M, int relu, int half_out) {
    extern __shared__ __align__(16) char smraw[];
    __nv_bfloat16* sAh = (__nv_bfloat16*)smraw;       // [128 m][152 k]
    __nv_bfloat16* sAl = sAh + PLANE;
    __nv_bfloat16* sBh = sAl + PLANE;                 // [128 n][152 k] (= W^T)
    __nv_bfloat16* sBl = sBh + PLANE;

    const int tid = threadIdx.x;
    const int m0 = blockIdx.x * 128;

    // ---- stage A tile: rows m0..m0+127, k 0..143, hi/lo split ----
    for (int idx = tid; idx < 128 * 72; idx += 256) {     // 72 float2 per row
        int r = idx / 72;
        int kc = (idx - r * 72) * 2;
        int gr = m0 + r;
        float2 v = make_float2(0.f, 0.f);
        if (gr < M) v = *(const float2*)(A + (size_t)gr * KDIM + kc);
        __nv_bfloat16 h0 = __float2bfloat16(v.x);
        __nv_bfloat16 h1 = __float2bfloat16(v.y);
        __nv_bfloat16 l0 = __float2bfloat16(v.x - __bfloat162float(h0));
        __nv_bfloat16 l1 = __float2bfloat16(v.y - __bfloat162float(h1));
        int o = r * SM_STRIDE + kc;
        *(uint32_t*)(sAh + o) = pack_bf16x2(h0, h1);
        *(uint32_t*)(sAl + o) = pack_bf16x2(l0, l1);
    }
    // ---- stage B tile: B^T[n][k] = W[k][n], hi/lo split ----
    for (int idx = tid; idx < KDIM * 128; idx += 256) {
        int k = idx >> 7;          // W row
        int n = idx & 127;         // W col (coalesced global read)
        float v = W[idx];
        __nv_bfloat16 h = __float2bfloat16(v);
        __nv_bfloat16 l = __float2bfloat16(v - __bfloat162float(h));
        int o = n * SM_STRIDE + k;
        sBh[o] = h;
        sBl[o] = l;
    }
    __syncthreads();

    // ---- mma mainloop ----
    const int wid = tid >> 5;
    const int lane = tid & 31;
    const int g = lane >> 2;        // group id (0..7)
    const int t = lane & 3;         // thread in group
    const int wm = (wid >> 2) * 64; // warp M offset (0/64)
    const int wn = (wid & 3) * 32;  // warp N offset (0/32/64/96)

    float acc[4][4][4];
#pragma unroll
    for (int i = 0; i < 4; i++)
#pragma unroll
        for (int j = 0; j < 4; j++)
#pragma unroll
            for (int q = 0; q < 4; q++) acc[i][j][q] = 0.f;

#pragma unroll
    for (int ks = 0; ks < 9; ks++) {
        const int kb = ks * 16;     // k base (bf16 elems)
        uint32_t ah[4][4], al[4][4], bh[4][2], bl[4][2];
#pragma unroll
        for (int i = 0; i < 4; i++) {
            int r = wm + i * 16;
            int o0 = (r + g) * SM_STRIDE + kb + 2 * t;
            int o1 = (r + g + 8) * SM_STRIDE + kb + 2 * t;
            ah[i][0] = *(const uint32_t*)(sAh + o0);
            ah[i][1] = *(const uint32_t*)(sAh + o1);
            ah[i][2] = *(const uint32_t*)(sAh + o0 + 8);
            ah[i][3] = *(const uint32_t*)(sAh + o1 + 8);
            al[i][0] = *(const uint32_t*)(sAl + o0);
            al[i][1] = *(const uint32_t*)(sAl + o1);
            al[i][2] = *(const uint32_t*)(sAl + o0 + 8);
            al[i][3] = *(const uint32_t*)(sAl + o1 + 8);
        }
#pragma unroll
        for (int j = 0; j < 4; j++) {
            int n = wn + j * 8 + g;
            int o = n * SM_STRIDE + kb + 2 * t;
            bh[j][0] = *(const uint32_t*)(sBh + o);
            bh[j][1] = *(const uint32_t*)(sBh + o + 8);
            bl[j][0] = *(const uint32_t*)(sBl + o);
            bl[j][1] = *(const uint32_t*)(sBl + o + 8);
        }
#pragma unroll
        for (int i = 0; i < 4; i++)
#pragma unroll
            for (int j = 0; j < 4; j++) {
                MMA16816(acc[i][j], ah[i], bh[j]);
                MMA16816(acc[i][j], ah[i], bl[j]);
                MMA16816(acc[i][j], al[i], bh[j]);
            }
    }

    // ---- epilogue: bias + relu; fp16 (layer1) or fp32 (layer2) stores ----
#pragma unroll
    for (int j = 0; j < 4; j++) {
        int c = wn + j * 8 + 2 * t;
        float2 bb = *(const float2*)(bias + c);
#pragma unroll
        for (int i = 0; i < 4; i++) {
            int r0 = m0 + wm + i * 16 + g;
            float v0 = acc[i][j][0] + bb.x;
            float v1 = acc[i][j][1] + bb.y;
            float v2 = acc[i][j][2] + bb.x;
            float v3 = acc[i][j][3] + bb.y;
            if (relu) {
                v0 = fmaxf(v0, 0.f); v1 = fmaxf(v1, 0.f);
                v2 = fmaxf(v2, 0.f); v3 = fmaxf(v3, 0.f);
            }
            if (half_out) {
                if (r0 < M)
                    *(__half2*)(Ch + (size_t)r0 * 128 + c) = __floats2half2_rn(v0, v1);
                if (r0 + 8 < M)
                    *(__half2*)(Ch + (size_t)(r0 + 8) * 128 + c) = __floats2half2_rn(v2, v3);
            } else {
                if (r0 < M)
                    *(float2*)(Cf + (size_t)r0 * 128 + c) = make_float2(v0, v1);
                if (r0 + 8 < M)
                    *(float2*)(Cf + (size_t)(r0 + 8) * 128 + c) = make_float2(v2, v3);
            }
        }
    }
}

// ---------------- launch ----------------
extern "C" void kernel_launch(void* const* d_in, const int* in_sizes, int n_in,
                              void* d_out, int out_size) {
    const float* x  = (const float*)d_in[0];
    const int*   ei = (const int*)d_in[1];
    const float* ea = (const float*)d_in[2];
    const float* W1 = (const float*)d_in[3];
    const float* b1 = (const float*)d_in[4];
    const float* W2 = (const float*)d_in[5];
    const float* b2 = (const float*)d_in[6];
    float* out = (float*)d_out;

    const int NB_SCAN = (N_NODES + 511) / 512;       // 98
    const int EB = (N_EDGES + 255) / 256;            // 3125
    const int AGG_B = (N_NODES * 32 + 255) / 256;    // 6250 (warp per node)
    const int GEMM_B = (N_NODES + 127) / 128;        // 391
    const int CVT_B = (N_NODES * NODE_IN / 4) / 256; // 6250

    void* p;
    cudaGetSymbolAddress(&p, g_A);  float*  s_A  = (float*)p;
    cudaGetSymbolAddress(&p, g_hx); __half* s_hx = (__half*)p;

    cudaFuncSetAttribute(k_gemm_mma, cudaFuncAttributeMaxDynamicSharedMemorySize,
                         GEMM_DYN_SMEM);

    k_init<<<(N_NODES + 255) / 256, 256>>>(ei);
    k_cvt<<<CVT_B, 256>>>(x);                 // x -> fp16 (no CSR dependency)
    k_hist<<<EB, 256>>>(ei);
    k_scan1<<<NB_SCAN, 512>>>();
    k_scan23<<<NB_SCAN, 512>>>(NB_SCAN);
    k_scatter<<<EB, 256>>>(ei);

    // layer 1: aggregate fp16 x + fp32 edge_attr, GEMM (relu) -> fp16 h in g_hx
    k_agg<true><<<AGG_B, 256>>>(ea);
    k_gemm_mma<<<GEMM_B, 256, GEMM_DYN_SMEM>>>(s_A, W1, b1, nullptr, s_hx,
                                               N_NODES, 1, 1);

    // layer 2: aggregate fp16 h into cols 0..127 (edge cols preserved), GEMM -> out
    k_agg<false><<<AGG_B, 256>>>(nullptr);
    k_gemm_mma<<<GEMM_B, 256, GEMM_DYN_SMEM>>>(s_A, W2, b2, out, nullptr,
                                               N_NODES, 0, 0);
}

// round 16
// speedup vs baseline: 1.4090x; 1.0298x over previous
#include <cuda_runtime.h>
#include <cuda_bf16.h>
#include <cuda_fp16.h>
#include <cstdint>

#define N_NODES 50000
#define N_EDGES 800000
#define NODE_IN 128
#define EDGE_IN 16
#define HIDDEN  128
#define OUT_DIM 128
#define KDIM    (NODE_IN + EDGE_IN)   // 144

// ---------------- scratch (device globals; no allocation allowed) ----------------
__device__ __align__(16) float g_A[(size_t)N_NODES * KDIM];     // [aggX | aggE], stride 144
__device__ __align__(16) __half g_hx[(size_t)N_NODES * NODE_IN]; // fp16 features (x, then h)
__device__ int g_count[N_NODES];
__device__ int g_rowstart[N_NODES];
__device__ int g_cursor[N_NODES];
__device__ __align__(8) int2 g_es[N_EDGES];   // {src, edge}, sorted by dst
__device__ int g_blocksums[128];
__device__ int g_is64;

__device__ __forceinline__ int load_idx(const int* ei, size_t elem, int is64) {
    return is64 ? ei[2 * elem] : ei[elem];
}

// ---------------- fused: fp32->fp16 convert + zero counts + dtype detect -----
// 6250 blocks: every thread converts one float4 of x; blocks 0..195 also zero
// g_count; the last block does the int64/int32 detect (odd words all zero).
__global__ __launch_bounds__(256) void k_cvt(const float* __restrict__ x,
                                             const int* __restrict__ ei) {
    int gid = blockIdx.x * blockDim.x + threadIdx.x;

    float4 v = ((const float4*)x)[gid];
    __half2 p0 = __floats2half2_rn(v.x, v.y);
    __half2 p1 = __floats2half2_rn(v.z, v.w);
    uint2 o;
    o.x = *(uint32_t*)&p0;
    o.y = *(uint32_t*)&p1;
    ((uint2*)g_hx)[gid] = o;

    if (gid < N_NODES) g_count[gid] = 0;

    if (blockIdx.x == gridDim.x - 1) {
        __shared__ int found;
        if (threadIdx.x == 0) found = 0;
        __syncthreads();
        for (int k = threadIdx.x; k < 4096; k += blockDim.x)
            if (ei[2 * k + 1] != 0) atomicOr(&found, 1);
        __syncthreads();
        if (threadIdx.x == 0) g_is64 = found ? 0 : 1;
    }
}

// ---------------- hist: 2 edges/thread, vectorized dst load ----------------
__global__ void k_hist(const int* __restrict__ ei) {
    int e0 = (blockIdx.x * blockDim.x + threadIdx.x) * 2;
    if (e0 >= N_EDGES) return;
    int is64 = g_is64;
    int d0, d1;
    if (is64) {
        // dst[e0], dst[e0+1] as two int64s = one 16B load (e0 even -> aligned)
        int4 v = *(const int4*)(ei + 2 * (size_t)N_EDGES + 2 * (size_t)e0);
        d0 = v.x; d1 = v.z;
    } else {
        int2 v = *(const int2*)(ei + (size_t)N_EDGES + e0);
        d0 = v.x; d1 = v.y;
    }
    atomicAdd(&g_count[d0], 1);
    atomicAdd(&g_count[d1], 1);
}

// ---------------- CSR scans ----------------
__global__ void k_scan1() {
    __shared__ int s[512];
    int t = threadIdx.x;
    int i = blockIdx.x * 512 + t;
    int v = (i < N_NODES) ? g_count[i] : 0;
    s[t] = v;
    __syncthreads();
    for (int off = 1; off < 512; off <<= 1) {
        int tmp = (t >= off) ? s[t - off] : 0;
        __syncthreads();
        s[t] += tmp;
        __syncthreads();
    }
    if (i < N_NODES) g_rowstart[i] = s[t] - v;
    if (t == 511) g_blocksums[blockIdx.x] = s[511];
}

// fused scan2+scan3 with UNIFORM barriers.
__global__ void k_scan23(int nblocks) {
    __shared__ int s[128];
    __shared__ int s_off;
    int t = threadIdx.x;
    if (t < 128) s[t] = (t < nblocks) ? g_blocksums[t] : 0;
    __syncthreads();
    for (int off = 1; off < 128; off <<= 1) {
        int tmp = (t < 128 && t >= off) ? s[t - off] : 0;
        __syncthreads();
        if (t < 128 && t >= off) s[t] += tmp;
        __syncthreads();
    }
    if (t == 0) s_off = (blockIdx.x > 0) ? s[blockIdx.x - 1] : 0;
    __syncthreads();
    int i = blockIdx.x * 512 + t;
    if (i < N_NODES) {
        int r = g_rowstart[i] + s_off;
        g_rowstart[i] = r;
        g_cursor[i] = r;
    }
}

// ---------------- scatter: one int2 store per edge ----------------
__global__ void k_scatter(const int* __restrict__ ei) {
    int e = blockIdx.x * blockDim.x + threadIdx.x;
    if (e >= N_EDGES) return;
    int is64 = g_is64;
    int d = load_idx(ei, (size_t)N_EDGES + e, is64);
    int s = load_idx(ei, (size_t)e, is64);
    int pos = atomicAdd(&g_cursor[d], 1);
    g_es[pos] = make_int2(s, e);
}

// ---------------- aggregation: warp per node, fp16 gather --------------------
// Sums src-node fp16 features (128 halfs; lane L owns uint2 index L of 32)
// into g_A[:, 0:128] with fp32 accumulation. If WITH_EA, lanes 0..15 also sum
// edge_attr (16 f32) into g_A[:, 128:144]. Index stream is one int2 per edge.
template <bool WITH_EA>
__global__ __launch_bounds__(256) void k_agg(const float* __restrict__ ea) {
    int warp = (blockIdx.x * blockDim.x + threadIdx.x) >> 5;
    int lane = threadIdx.x & 31;
    if (warp >= N_NODES) return;

    int start = g_rowstart[warp];
    int cnt = g_count[warp];
    const uint2* xf = (const uint2*)g_hx;   // 32 uint2 per 128-half row

    float4 acc = make_float4(0.f, 0.f, 0.f, 0.f);
    float eacc = 0.f;
    bool do_ea = WITH_EA && (lane < 16);

    // two-stage pipeline: prefetch next {src, edge} while consuming current
    int2 cur = make_int2(0, 0);
    if (cnt > 0) cur = g_es[start];
    for (int i = 0; i < cnt; i++) {
        int2 nxt = (i + 1 < cnt) ? g_es[start + i + 1] : make_int2(0, 0);
        uint2 v = __ldcg(xf + (size_t)cur.x * 32 + lane);   // L2-only gather
        __half2 p0 = *(__half2*)&v.x;
        __half2 p1 = *(__half2*)&v.y;
        float2 f0 = __half22float2(p0);
        float2 f1 = __half22float2(p1);
        acc.x += f0.x; acc.y += f0.y; acc.z += f1.x; acc.w += f1.y;
        if (do_ea) eacc += ea[(size_t)cur.y * EDGE_IN + lane];
        cur = nxt;
    }

    ((float4*)(g_A + (size_t)warp * KDIM))[lane] = acc;
    if (do_ea) g_A[(size_t)warp * KDIM + NODE_IN + lane] = eacc;
}

// ================= tensor-core GEMM via mma.sync (sm_80+ path) ================
// C[M,128] = A[M,144] @ W[144,128] + b, optional relu.
// bf16 3-pass split: A=Ah+Al, B=Bh+Bl; D = Ah*Bh + Ah*Bl + Al*Bh, fp32 accum.
// Whole K resident in SMEM. Padded stride 152 bf16 -> conflict-free frag loads.
// half_out: store relu result as fp16 into Ch (layer 1); else fp32 into Cf.

#define SM_STRIDE 152                       // bf16 elements per row (padded)
#define PLANE     (128 * SM_STRIDE)         // elements per plane
#define GEMM_DYN_SMEM (4 * PLANE * 2)       // 4 planes of bf16 = 155648 B

#define MMA16816(d, a, b)                                                     \
    asm volatile(                                                             \
        "mma.sync.aligned.m16n8k16.row.col.f32.bf16.bf16.f32 "                \
        "{%0,%1,%2,%3}, {%4,%5,%6,%7}, {%8,%9}, {%0,%1,%2,%3};"               \
        : "+f"((d)[0]), "+f"((d)[1]), "+f"((d)[2]), "+f"((d)[3])              \
        : "r"((a)[0]), "r"((a)[1]), "r"((a)[2]), "r"((a)[3]),                 \
          "r"((b)[0]), "r"((b)[1]))

__device__ __forceinline__ uint32_t pack_bf16x2(__nv_bfloat16 lo, __nv_bfloat16 hi) {
    __nv_bfloat162 p = __halves2bfloat162(lo, hi);   // .x = lo addr half
    return *(uint32_t*)&p;
}

__global__ __launch_bounds__(256, 1)
void k_gemm_mma(const float* __restrict__ A,
                const float* __restrict__ W,
                const float* __restrict__ bias,
                float* __restrict__ Cf,
                __half* __restrict__ Ch,
                int M, int relu, int half_out) {
    extern __shared__ __align__(16) char smraw[];
    __nv_bfloat16* sAh = (__nv_bfloat16*)smraw;       // [128 m][152 k]
    __nv_bfloat16* sAl = sAh + PLANE;
    __nv_bfloat16* sBh = sAl + PLANE;                 // [128 n][152 k] (= W^T)
    __nv_bfloat16* sBl = sBh + PLANE;

    const int tid = threadIdx.x;
    const int m0 = blockIdx.x * 128;

    // ---- stage A tile: rows m0..m0+127, k 0..143, hi/lo split ----
    for (int idx = tid; idx < 128 * 72; idx += 256) {     // 72 float2 per row
        int r = idx / 72;
        int kc = (idx - r * 72) * 2;
        int gr = m0 + r;
        float2 v = make_float2(0.f, 0.f);
        if (gr < M) v = *(const float2*)(A + (size_t)gr * KDIM + kc);
        __nv_bfloat16 h0 = __float2bfloat16(v.x);
        __nv_bfloat16 h1 = __float2bfloat16(v.y);
        __nv_bfloat16 l0 = __float2bfloat16(v.x - __bfloat162float(h0));
        __nv_bfloat16 l1 = __float2bfloat16(v.y - __bfloat162float(h1));
        int o = r * SM_STRIDE + kc;
        *(uint32_t*)(sAh + o) = pack_bf16x2(h0, h1);
        *(uint32_t*)(sAl + o) = pack_bf16x2(l0, l1);
    }
    // ---- stage B tile: B^T[n][k] = W[k][n], hi/lo split ----
    for (int idx = tid; idx < KDIM * 128; idx += 256) {
        int k = idx >> 7;          // W row
        int n = idx & 127;         // W col (coalesced global read)
        float v = W[idx];
        __nv_bfloat16 h = __float2bfloat16(v);
        __nv_bfloat16 l = __float2bfloat16(v - __bfloat162float(h));
        int o = n * SM_STRIDE + k;
        sBh[o] = h;
        sBl[o] = l;
    }
    __syncthreads();

    // ---- mma mainloop ----
    const int wid = tid >> 5;
    const int lane = tid & 31;
    const int g = lane >> 2;        // group id (0..7)
    const int t = lane & 3;         // thread in group
    const int wm = (wid >> 2) * 64; // warp M offset (0/64)
    const int wn = (wid & 3) * 32;  // warp N offset (0/32/64/96)

    float acc[4][4][4];
#pragma unroll
    for (int i = 0; i < 4; i++)
#pragma unroll
        for (int j = 0; j < 4; j++)
#pragma unroll
            for (int q = 0; q < 4; q++) acc[i][j][q] = 0.f;

#pragma unroll
    for (int ks = 0; ks < 9; ks++) {
        const int kb = ks * 16;     // k base (bf16 elems)
        uint32_t ah[4][4], al[4][4], bh[4][2], bl[4][2];
#pragma unroll
        for (int i = 0; i < 4; i++) {
            int r = wm + i * 16;
            int o0 = (r + g) * SM_STRIDE + kb + 2 * t;
            int o1 = (r + g + 8) * SM_STRIDE + kb + 2 * t;
            ah[i][0] = *(const uint32_t*)(sAh + o0);
            ah[i][1] = *(const uint32_t*)(sAh + o1);
            ah[i][2] = *(const uint32_t*)(sAh + o0 + 8);
            ah[i][3] = *(const uint32_t*)(sAh + o1 + 8);
            al[i][0] = *(const uint32_t*)(sAl + o0);
            al[i][1] = *(const uint32_t*)(sAl + o1);
            al[i][2] = *(const uint32_t*)(sAl + o0 + 8);
            al[i][3] = *(const uint32_t*)(sAl + o1 + 8);
        }
#pragma unroll
        for (int j = 0; j < 4; j++) {
            int n = wn + j * 8 + g;
            int o = n * SM_STRIDE + kb + 2 * t;
            bh[j][0] = *(const uint32_t*)(sBh + o);
            bh[j][1] = *(const uint32_t*)(sBh + o + 8);
            bl[j][0] = *(const uint32_t*)(sBl + o);
            bl[j][1] = *(const uint32_t*)(sBl + o + 8);
        }
#pragma unroll
        for (int i = 0; i < 4; i++)
#pragma unroll
            for (int j = 0; j < 4; j++) {
                MMA16816(acc[i][j], ah[i], bh[j]);
                MMA16816(acc[i][j], ah[i], bl[j]);
                MMA16816(acc[i][j], al[i], bh[j]);
            }
    }

    // ---- epilogue: bias + relu; fp16 (layer1) or fp32 (layer2) stores ----
#pragma unroll
    for (int j = 0; j < 4; j++) {
        int c = wn + j * 8 + 2 * t;
        float2 bb = *(const float2*)(bias + c);
#pragma unroll
        for (int i = 0; i < 4; i++) {
            int r0 = m0 + wm + i * 16 + g;
            float v0 = acc[i][j][0] + bb.x;
            float v1 = acc[i][j][1] + bb.y;
            float v2 = acc[i][j][2] + bb.x;
            float v3 = acc[i][j][3] + bb.y;
            if (relu) {
                v0 = fmaxf(v0, 0.f); v1 = fmaxf(v1, 0.f);
                v2 = fmaxf(v2, 0.f); v3 = fmaxf(v3, 0.f);
            }
            if (half_out) {
                if (r0 < M)
                    *(__half2*)(Ch + (size_t)r0 * 128 + c) = __floats2half2_rn(v0, v1);
                if (r0 + 8 < M)
                    *(__half2*)(Ch + (size_t)(r0 + 8) * 128 + c) = __floats2half2_rn(v2, v3);
            } else {
                if (r0 < M)
                    *(float2*)(Cf + (size_t)r0 * 128 + c) = make_float2(v0, v1);
                if (r0 + 8 < M)
                    *(float2*)(Cf + (size_t)(r0 + 8) * 128 + c) = make_float2(v2, v3);
            }
        }
    }
}

// ---------------- launch ----------------
extern "C" void kernel_launch(void* const* d_in, const int* in_sizes, int n_in,
                              void* d_out, int out_size) {
    const float* x  = (const float*)d_in[0];
    const int*   ei = (const int*)d_in[1];
    const float* ea = (const float*)d_in[2];
    const float* W1 = (const float*)d_in[3];
    const float* b1 = (const float*)d_in[4];
    const float* W2 = (const float*)d_in[5];
    const float* b2 = (const float*)d_in[6];
    float* out = (float*)d_out;

    const int NB_SCAN = (N_NODES + 511) / 512;       // 98
    const int EB = (N_EDGES + 255) / 256;            // 3125
    const int HB = (N_EDGES / 2 + 255) / 256;        // 1563 (2 edges/thread)
    const int AGG_B = (N_NODES * 32 + 255) / 256;    // 6250 (warp per node)
    const int GEMM_B = (N_NODES + 127) / 128;        // 391
    const int CVT_B = (N_NODES * NODE_IN / 4) / 256; // 6250

    void* p;
    cudaGetSymbolAddress(&p, g_A);  float*  s_A  = (float*)p;
    cudaGetSymbolAddress(&p, g_hx); __half* s_hx = (__half*)p;

    cudaFuncSetAttribute(k_gemm_mma, cudaFuncAttributeMaxDynamicSharedMemorySize,
                         GEMM_DYN_SMEM);

    k_cvt<<<CVT_B, 256>>>(x, ei);        // cvt + zero counts + dtype detect
    k_hist<<<HB, 256>>>(ei);
    k_scan1<<<NB_SCAN, 512>>>();
    k_scan23<<<NB_SCAN, 512>>>(NB_SCAN);
    k_scatter<<<EB, 256>>>(ei);

    // layer 1: aggregate fp16 x + fp32 edge_attr, GEMM (relu) -> fp16 h in g_hx
    k_agg<true><<<AGG_B, 256>>>(ea);
    k_gemm_mma<<<GEMM_B, 256, GEMM_DYN_SMEM>>>(s_A, W1, b1, nullptr, s_hx,
                                               N_NODES, 1, 1);

    // layer 2: aggregate fp16 h into cols 0..127 (edge cols preserved), GEMM -> out
    k_agg<false><<<AGG_B, 256>>>(nullptr);
    k_gemm_mma<<<GEMM_B, 256, GEMM_DYN_SMEM>>>(s_A, W2, b2, out, nullptr,
                                               N_NODES, 0, 0);
}

// round 17
// speedup vs baseline: 1.4188x; 1.0070x over previous
#include <cuda_runtime.h>
#include <cuda_bf16.h>
#include <cuda_fp16.h>
#include <cstdint>

#define N_NODES 50000
#define N_EDGES 800000
#define NODE_IN 128
#define EDGE_IN 16
#define HIDDEN  128
#define OUT_DIM 128
#define KDIM    (NODE_IN + EDGE_IN)   // 144
#define SCAN_TILES 98                 // ceil(50000 / 512)

// ---------------- scratch (device globals; no allocation allowed) ----------------
__device__ __align__(16) float g_A[(size_t)N_NODES * KDIM];     // [aggX | aggE], stride 144
__device__ __align__(16) __half g_hx[(size_t)N_NODES * NODE_IN]; // fp16 features (x, then h)
__device__ int g_count[N_NODES];
__device__ int g_rowstart[N_NODES];
__device__ int g_cursor[N_NODES];
__device__ __align__(8) int2 g_es[N_EDGES];   // {src, edge}, sorted by dst
__device__ int g_tile_agg[SCAN_TILES];
__device__ int g_tile_incl[SCAN_TILES];
__device__ int g_tile_flag[SCAN_TILES];   // 0 none, 1 agg ready, 2 incl ready
__device__ int g_is64;

__device__ __forceinline__ int load_idx(const int* ei, size_t elem, int is64) {
    return is64 ? ei[2 * elem] : ei[elem];
}

// ---------------- fused: fp32->fp16 convert + zero counts/flags + detect -----
// 6250 blocks: every thread converts one float4 of x; low gids also zero
// g_count and the scan tile flags; the last block does the dtype detect.
__global__ __launch_bounds__(256) void k_cvt(const float* __restrict__ x,
                                             const int* __restrict__ ei) {
    int gid = blockIdx.x * blockDim.x + threadIdx.x;

    float4 v = ((const float4*)x)[gid];
    __half2 p0 = __floats2half2_rn(v.x, v.y);
    __half2 p1 = __floats2half2_rn(v.z, v.w);
    uint2 o;
    o.x = *(uint32_t*)&p0;
    o.y = *(uint32_t*)&p1;
    ((uint2*)g_hx)[gid] = o;

    if (gid < N_NODES) g_count[gid] = 0;
    if (gid < SCAN_TILES) g_tile_flag[gid] = 0;

    if (blockIdx.x == gridDim.x - 1) {
        __shared__ int found;
        if (threadIdx.x == 0) found = 0;
        __syncthreads();
        for (int k = threadIdx.x; k < 4096; k += blockDim.x)
            if (ei[2 * k + 1] != 0) atomicOr(&found, 1);
        __syncthreads();
        if (threadIdx.x == 0) g_is64 = found ? 0 : 1;
    }
}

// ---------------- hist: 4 edges/thread, vectorized dst loads ----------------
__global__ void k_hist(const int* __restrict__ ei) {
    int e0 = (blockIdx.x * blockDim.x + threadIdx.x) * 4;
    if (e0 >= N_EDGES) return;
    int is64 = g_is64;
    int d0, d1, d2, d3;
    if (is64) {
        const int4* p = (const int4*)(ei + 2 * (size_t)N_EDGES + 2 * (size_t)e0);
        int4 a = p[0], b = p[1];
        d0 = a.x; d1 = a.z; d2 = b.x; d3 = b.z;
    } else {
        int4 a = *(const int4*)(ei + (size_t)N_EDGES + e0);
        d0 = a.x; d1 = a.y; d2 = a.z; d3 = a.w;
    }
    atomicAdd(&g_count[d0], 1);
    atomicAdd(&g_count[d1], 1);
    atomicAdd(&g_count[d2], 1);
    atomicAdd(&g_count[d3], 1);
}

// ---------------- single-pass scan: local scan + warp-parallel lookback ------
// 98 co-resident blocks (98 < 148 SMs -> no deadlock). Deterministic: prefix
// values are unique regardless of publish order. Flags zeroed by k_cvt.
__global__ __launch_bounds__(512) void k_scan() {
    __shared__ int s[512];
    __shared__ int s_excl;
    const int t = threadIdx.x;
    const int bid = blockIdx.x;
    const int i = bid * 512 + t;

    int v = (i < N_NODES) ? g_count[i] : 0;
    s[t] = v;
    __syncthreads();
    for (int off = 1; off < 512; off <<= 1) {
        int tmp = (t >= off) ? s[t - off] : 0;
        __syncthreads();
        s[t] += tmp;
        __syncthreads();
    }
    int local_excl = s[t] - v;
    int agg = s[511];

    // publish aggregate (or inclusive for tile 0)
    if (t == 0) {
        if (bid == 0) {
            g_tile_incl[0] = agg;
            __threadfence();
            g_tile_flag[0] = 2;
        } else {
            g_tile_agg[bid] = agg;
            __threadfence();
            g_tile_flag[bid] = 1;
        }
        s_excl = 0;
    }
    __syncthreads();

    // warp 0: decoupled lookback over predecessors, 32 at a time
    if (bid > 0 && t < 32) {
        int lane = t;
        int excl = 0;
        int j = bid - 1;
        while (true) {
            int idx = j - lane;
            int flag = 0, val = 0;
            if (idx >= 0) {
                do { flag = *(volatile int*)&g_tile_flag[idx]; } while (flag == 0);
                __threadfence();
                val = (flag == 2) ? g_tile_incl[idx] : g_tile_agg[idx];
            }
            unsigned m2 = __ballot_sync(0xffffffffu, idx >= 0 && flag == 2);
            if (m2) {
                int lead = __ffs(m2) - 1;   // smallest lane = largest idx with incl
                int c = (lane <= lead) ? val : 0;
                for (int o = 16; o; o >>= 1) c += __shfl_down_sync(0xffffffffu, c, o);
                c = __shfl_sync(0xffffffffu, c, 0);
                excl += c;
                break;
            } else {
                int c = (idx >= 0) ? val : 0;
                for (int o = 16; o; o >>= 1) c += __shfl_down_sync(0xffffffffu, c, o);
                c = __shfl_sync(0xffffffffu, c, 0);
                excl += c;
                j -= 32;
            }
        }
        if (lane == 0) {
            g_tile_incl[bid] = excl + agg;
            __threadfence();
            g_tile_flag[bid] = 2;
            s_excl = excl;
        }
    }
    __syncthreads();

    if (i < N_NODES) {
        int r = local_excl + s_excl;
        g_rowstart[i] = r;
        g_cursor[i] = r;
    }
}

// ---------------- scatter: one int2 store per edge ----------------
__global__ void k_scatter(const int* __restrict__ ei) {
    int e = blockIdx.x * blockDim.x + threadIdx.x;
    if (e >= N_EDGES) return;
    int is64 = g_is64;
    int d = load_idx(ei, (size_t)N_EDGES + e, is64);
    int s = load_idx(ei, (size_t)e, is64);
    int pos = atomicAdd(&g_cursor[d], 1);
    g_es[pos] = make_int2(s, e);
}

// ---------------- aggregation: warp per node, fp16 gather --------------------
// Sums src-node fp16 features (128 halfs; lane L owns uint2 index L of 32)
// into g_A[:, 0:128] with fp32 accumulation. If WITH_EA, lanes 0..15 also sum
// edge_attr (16 f32) into g_A[:, 128:144]. Index stream is one int2 per edge.
template <bool WITH_EA>
__global__ __launch_bounds__(256) void k_agg(const float* __restrict__ ea) {
    int warp = (blockIdx.x * blockDim.x + threadIdx.x) >> 5;
    int lane = threadIdx.x & 31;
    if (warp >= N_NODES) return;

    int start = g_rowstart[warp];
    int cnt = g_count[warp];
    const uint2* xf = (const uint2*)g_hx;   // 32 uint2 per 128-half row

    float4 acc = make_float4(0.f, 0.f, 0.f, 0.f);
    float eacc = 0.f;
    bool do_ea = WITH_EA && (lane < 16);

    // two-stage pipeline: prefetch next {src, edge} while consuming current
    int2 cur = make_int2(0, 0);
    if (cnt > 0) cur = g_es[start];
    for (int i = 0; i < cnt; i++) {
        int2 nxt = (i + 1 < cnt) ? g_es[start + i + 1] : make_int2(0, 0);
        uint2 v = __ldcg(xf + (size_t)cur.x * 32 + lane);   // L2-only gather
        __half2 p0 = *(__half2*)&v.x;
        __half2 p1 = *(__half2*)&v.y;
        float2 f0 = __half22float2(p0);
        float2 f1 = __half22float2(p1);
        acc.x += f0.x; acc.y += f0.y; acc.z += f1.x; acc.w += f1.y;
        if (do_ea) eacc += ea[(size_t)cur.y * EDGE_IN + lane];
        cur = nxt;
    }

    ((float4*)(g_A + (size_t)warp * KDIM))[lane] = acc;
    if (do_ea) g_A[(size_t)warp * KDIM + NODE_IN + lane] = eacc;
}

// ================= tensor-core GEMM via mma.sync (sm_80+ path) ================
// C[M,128] = A[M,144] @ W[144,128] + b, optional relu.
// bf16 3-pass split: A=Ah+Al, B=Bh+Bl; D = Ah*Bh + Ah*Bl + Al*Bh, fp32 accum.
// Whole K resident in SMEM. Padded stride 152 bf16 -> conflict-free frag loads.
// half_out: store relu result as fp16 into Ch (layer 1); else fp32 into Cf.

#define SM_STRIDE 152                       // bf16 elements per row (padded)
#define PLANE     (128 * SM_STRIDE)         // elements per plane
#define GEMM_DYN_SMEM (4 * PLANE * 2)       // 4 planes of bf16 = 155648 B

#define MMA16816(d, a, b)                                                     \
    asm volatile(                                                             \
        "mma.sync.aligned.m16n8k16.row.col.f32.bf16.bf16.f32 "                \
        "{%0,%1,%2,%3}, {%4,%5,%6,%7}, {%8,%9}, {%0,%1,%2,%3};"               \
        : "+f"((d)[0]), "+f"((d)[1]), "+f"((d)[2]), "+f"((d)[3])              \
        : "r"((a)[0]), "r"((a)[1]), "r"((a)[2]), "r"((a)[3]),                 \
          "r"((b)[0]), "r"((b)[1]))

__device__ __forceinline__ uint32_t pack_bf16x2(__nv_bfloat16 lo, __nv_bfloat16 hi) {
    __nv_bfloat162 p = __halves2bfloat162(lo, hi);   // .x = lo addr half
    return *(uint32_t*)&p;
}

__global__ __launch_bounds__(256, 1)
void k_gemm_mma(const float* __restrict__ A,
                const float* __restrict__ W,
                const float* __restrict__ bias,
                float* __restrict__ Cf,
                __half* __restrict__ Ch,
                int M, int relu, int half_out) {
    extern __shared__ __align__(16) char smraw[];
    __nv_bfloat16* sAh = (__nv_bfloat16*)smraw;       // [128 m][152 k]
    __nv_bfloat16* sAl = sAh + PLANE;
    __nv_bfloat16* sBh = sAl + PLANE;                 // [128 n][152 k] (= W^T)
    __nv_bfloat16* sBl = sBh + PLANE;

    const int tid = threadIdx.x;
    const int m0 = blockIdx.x * 128;

    // ---- stage A tile: rows m0..m0+127, k 0..143, hi/lo split ----
    for (int idx = tid; idx < 128 * 72; idx += 256) {     // 72 float2 per row
        int r = idx / 72;
        int kc = (idx - r * 72) * 2;
        int gr = m0 + r;
        float2 v = make_float2(0.f, 0.f);
        if (gr < M) v = *(const float2*)(A + (size_t)gr * KDIM + kc);
        __nv_bfloat16 h0 = __float2bfloat16(v.x);
        __nv_bfloat16 h1 = __float2bfloat16(v.y);
        __nv_bfloat16 l0 = __float2bfloat16(v.x - __bfloat162float(h0));
        __nv_bfloat16 l1 = __float2bfloat16(v.y - __bfloat162float(h1));
        int o = r * SM_STRIDE + kc;
        *(uint32_t*)(sAh + o) = pack_bf16x2(h0, h1);
        *(uint32_t*)(sAl + o) = pack_bf16x2(l0, l1);
    }
    // ---- stage B tile: B^T[n][k] = W[k][n], hi/lo split ----
    for (int idx = tid; idx < KDIM * 128; idx += 256) {
        int k = idx >> 7;          // W row
        int n = idx & 127;         // W col (coalesced global read)
        float v = W[idx];
        __nv_bfloat16 h = __float2bfloat16(v);
        __nv_bfloat16 l = __float2bfloat16(v - __bfloat162float(h));
        int o = n * SM_STRIDE + k;
        sBh[o] = h;
        sBl[o] = l;
    }
    __syncthreads();

    // ---- mma mainloop ----
    const int wid = tid >> 5;
    const int lane = tid & 31;
    const int g = lane >> 2;        // group id (0..7)
    const int t = lane & 3;         // thread in group
    const int wm = (wid >> 2) * 64; // warp M offset (0/64)
    const int wn = (wid & 3) * 32;  // warp N offset (0/32/64/96)

    float acc[4][4][4];
#pragma unroll
    for (int i = 0; i < 4; i++)
#pragma unroll
        for (int j = 0; j < 4; j++)
#pragma unroll
            for (int q = 0; q < 4; q++) acc[i][j][q] = 0.f;

#pragma unroll
    for (int ks = 0; ks < 9; ks++) {
        const int kb = ks * 16;     // k base (bf16 elems)
        uint32_t ah[4][4], al[4][4], bh[4][2], bl[4][2];
#pragma unroll
        for (int i = 0; i < 4; i++) {
            int r = wm + i * 16;
            int o0 = (r + g) * SM_STRIDE + kb + 2 * t;
            int o1 = (r + g + 8) * SM_STRIDE + kb + 2 * t;
            ah[i][0] = *(const uint32_t*)(sAh + o0);
            ah[i][1] = *(const uint32_t*)(sAh + o1);
            ah[i][2] = *(const uint32_t*)(sAh + o0 + 8);
            ah[i][3] = *(const uint32_t*)(sAh + o1 + 8);
            al[i][0] = *(const uint32_t*)(sAl + o0);
            al[i][1] = *(const uint32_t*)(sAl + o1);
            al[i][2] = *(const uint32_t*)(sAl + o0 + 8);
            al[i][3] = *(const uint32_t*)(sAl + o1 + 8);
        }
#pragma unroll
        for (int j = 0; j < 4; j++) {
            int n = wn + j * 8 + g;
            int o = n * SM_STRIDE + kb + 2 * t;
            bh[j][0] = *(const uint32_t*)(sBh + o);
            bh[j][1] = *(const uint32_t*)(sBh + o + 8);
            bl[j][0] = *(const uint32_t*)(sBl + o);
            bl[j][1] = *(const uint32_t*)(sBl + o + 8);
        }
#pragma unroll
        for (int i = 0; i < 4; i++)
#pragma unroll
            for (int j = 0; j < 4; j++) {
                MMA16816(acc[i][j], ah[i], bh[j]);
                MMA16816(acc[i][j], ah[i], bl[j]);
                MMA16816(acc[i][j], al[i], bh[j]);
            }
    }

    // ---- epilogue: bias + relu; fp16 (layer1) or fp32 (layer2) stores ----
#pragma unroll
    for (int j = 0; j < 4; j++) {
        int c = wn + j * 8 + 2 * t;
        float2 bb = *(const float2*)(bias + c);
#pragma unroll
        for (int i = 0; i < 4; i++) {
            int r0 = m0 + wm + i * 16 + g;
            float v0 = acc[i][j][0] + bb.x;
            float v1 = acc[i][j][1] + bb.y;
            float v2 = acc[i][j][2] + bb.x;
            float v3 = acc[i][j][3] + bb.y;
            if (relu) {
                v0 = fmaxf(v0, 0.f); v1 = fmaxf(v1, 0.f);
                v2 = fmaxf(v2, 0.f); v3 = fmaxf(v3, 0.f);
            }
            if (half_out) {
                if (r0 < M)
                    *(__half2*)(Ch + (size_t)r0 * 128 + c) = __floats2half2_rn(v0, v1);
                if (r0 + 8 < M)
                    *(__half2*)(Ch + (size_t)(r0 + 8) * 128 + c) = __floats2half2_rn(v2, v3);
            } else {
                if (r0 < M)
                    *(float2*)(Cf + (size_t)r0 * 128 + c) = make_float2(v0, v1);
                if (r0 + 8 < M)
                    *(float2*)(Cf + (size_t)(r0 + 8) * 128 + c) = make_float2(v2, v3);
            }
        }
    }
}

// ---------------- launch ----------------
extern "C" void kernel_launch(void* const* d_in, const int* in_sizes, int n_in,
                              void* d_out, int out_size) {
    const float* x  = (const float*)d_in[0];
    const int*   ei = (const int*)d_in[1];
    const float* ea = (const float*)d_in[2];
    const float* W1 = (const float*)d_in[3];
    const float* b1 = (const float*)d_in[4];
    const float* W2 = (const float*)d_in[5];
    const float* b2 = (const float*)d_in[6];
    float* out = (float*)d_out;

    const int EB = (N_EDGES + 255) / 256;            // 3125
    const int HB = (N_EDGES / 4 + 255) / 256;        // 782 (4 edges/thread)
    const int AGG_B = (N_NODES * 32 + 255) / 256;    // 6250 (warp per node)
    const int GEMM_B = (N_NODES + 127) / 128;        // 391
    const int CVT_B = (N_NODES * NODE_IN / 4) / 256; // 6250

    void* p;
    cudaGetSymbolAddress(&p, g_A);  float*  s_A  = (float*)p;
    cudaGetSymbolAddress(&p, g_hx); __half* s_hx = (__half*)p;

    cudaFuncSetAttribute(k_gemm_mma, cudaFuncAttributeMaxDynamicSharedMemorySize,
                         GEMM_DYN_SMEM);

    k_cvt<<<CVT_B, 256>>>(x, ei);        // cvt + zero counts/flags + detect
    k_hist<<<HB, 256>>>(ei);
    k_scan<<<SCAN_TILES, 512>>>();       // single-pass decoupled-lookback scan
    k_scatter<<<EB, 256>>>(ei);

    // layer 1: aggregate fp16 x + fp32 edge_attr, GEMM (relu) -> fp16 h in g_hx
    k_agg<true><<<AGG_B, 256>>>(ea);
    k_gemm_mma<<<GEMM_B, 256, GEMM_DYN_SMEM>>>(s_A, W1, b1, nullptr, s_hx,
                                               N_NODES, 1, 1);

    // layer 2: aggregate fp16 h into cols 0..127 (edge cols preserved), GEMM -> out
    k_agg<false><<<AGG_B, 256>>>(nullptr);
    k_gemm_mma<<<GEMM_B, 256, GEMM_DYN_SMEM>>>(s_A, W2, b2, out, nullptr,
                                               N_NODES, 0, 0);
}